// round 15
// baseline (speedup 1.0000x reference)
#include <cuda_runtime.h>
#include <cuda_bf16.h>
#include <cuda_fp16.h>
#include <stdint.h>

// Problem constants: N=100000 nodes, E=600000 edges, D=128.
#define N_MAX 100000
#define E_MAX 600000
#define DIM   128

// scan geometry
#define SC_BLK   256
#define SC_PER   8
#define SC_CHUNK (SC_BLK * SC_PER)            // 2048
#define SC_NBLK  ((N_MAX + SC_CHUNK - 1) / SC_CHUNK)   // 49 (must stay < 148 for co-residency)

// edge-kernel batching
#define EB 4

// ---- device scratch (no cudaMalloc allowed) ----
__device__ int   g_deg[N_MAX];
__device__ int   g_off[N_MAX + 1];
__device__ int   g_cur[N_MAX];
__device__ int   g_csr[E_MAX];
__device__ int   g_part[64];                                   // partial+1; 0 = not ready
__device__ __align__(16) __half2 g_featH[(size_t)N_MAX * 64];  // fp16 features
__device__ __align__(16) __half2 g_aggH[(size_t)N_MAX * 64];   // fp16 neighbor means
__device__ __align__(16) __half  g_WH[2 * 128 * DIM];          // [0]=W_l, [1]=W_r (row-major j,k)

// ---------------------------------------------------------------------------
// 1) histogram (4 edges/thread) + feature->fp16 convert + weight->fp16 convert
__global__ void hist_conv_kernel(const int* __restrict__ ei, int E,
                                 const float2* __restrict__ f2, int n2,
                                 const float* __restrict__ Wl,
                                 const float* __restrict__ Wr) {
    if (blockIdx.x == 0 && threadIdx.x < 64) g_part[threadIdx.x] = 0;

    int base = blockIdx.x * (256 * EB) + threadIdx.x;
    int d[EB];
#pragma unroll
    for (int k = 0; k < EB; ++k) {
        int i = base + k * 256;
        d[k] = (i < E) ? ei[E + i] : -1;
    }
#pragma unroll
    for (int k = 0; k < EB; ++k)
        if (d[k] >= 0 && d[k] < N_MAX) atomicAdd(&g_deg[d[k]], 1);

    int nth = gridDim.x * 256;
    int tid0 = blockIdx.x * 256 + threadIdx.x;
    for (int i = tid0; i < 2 * 128 * DIM; i += nth) {
        float v = (i < 128 * DIM) ? Wl[i] : Wr[i - 128 * DIM];
        g_WH[i] = __float2half_rn(v);
    }
    for (int i = tid0; i < n2; i += nth)
        g_featH[i] = __float22half2_rn(f2[i]);
}

// 2) single-pass offsets (co-resident spin on chunk partials)
__global__ void off_kernel(int n, int E, int nblk) {
    __shared__ int s_wsum[8];
    __shared__ int s_woff[8];
    __shared__ int s_total;
    __shared__ int sp[64];

    int t = threadIdx.x;
    int lane = t & 31, wid = t >> 5;
    int base = blockIdx.x * SC_CHUNK + t * SC_PER;

    int v[SC_PER];
    int sum = 0;
#pragma unroll
    for (int j = 0; j < SC_PER; ++j) {
        int i = base + j;
        v[j] = (i < n) ? g_deg[i] : 0;
        sum += v[j];
    }

    int inc = sum;
#pragma unroll
    for (int o = 1; o < 32; o <<= 1) {
        int x = __shfl_up_sync(0xffffffffu, inc, o);
        if (lane >= o) inc += x;
    }
    if (lane == 31) s_wsum[wid] = inc;
    __syncthreads();

    if (wid == 0 && lane < 8) {
        int wv = s_wsum[lane];
        int winc = wv;
#pragma unroll
        for (int o = 1; o < 8; o <<= 1) {
            int x = __shfl_up_sync(0xffu, winc, o);
            if (lane >= o) winc += x;
        }
        s_woff[lane] = winc - wv;
        if (lane == 7) s_total = winc;
    }
    __syncthreads();

    if (t == 0) atomicExch(&g_part[blockIdx.x], s_total + 1);

    if (t < 64) {
        int val = 0;
        if (t < nblk) {
            volatile int* gp = g_part;
            while ((val = gp[t]) == 0) { }
            val -= 1;
        }
        sp[t] = val;
    }
    __syncthreads();

#pragma unroll
    for (int o = 1; o < 64; o <<= 1) {
        int tmp = (t < 64 && t >= o) ? sp[t - o] : 0;
        __syncthreads();
        if (t < 64) sp[t] += tmp;
        __syncthreads();
    }
    int chunk_prefix = (blockIdx.x == 0) ? 0 : sp[blockIdx.x - 1];

    int run = chunk_prefix + s_woff[wid] + (inc - sum);
#pragma unroll
    for (int j = 0; j < SC_PER; ++j) {
        int i = base + j;
        if (i < n) {
            g_off[i] = run;
            g_cur[i] = run;
            run += v[j];
        }
    }
    if (blockIdx.x == 0 && t == 0) g_off[n] = E;
}

// 3) scatter src ids into CSR slots — 4 edges/thread
__global__ void scatter_kernel(const int* __restrict__ ei, int E) {
    int base = blockIdx.x * (256 * EB) + threadIdx.x;
    int src[EB], dst[EB];
#pragma unroll
    for (int k = 0; k < EB; ++k) {
        int i = base + k * 256;
        src[k] = (i < E) ? ei[i] : 0;
        dst[k] = (i < E) ? ei[E + i] : -1;
    }
#pragma unroll
    for (int k = 0; k < EB; ++k) {
        if (dst[k] >= 0 && dst[k] < N_MAX) {
            int pos = atomicAdd(&g_cur[dst[k]], 1);
            g_csr[pos] = src[k];
        }
    }
}

// 4) mean aggregation: 16 lanes/node, uint4 loads, HADD2 accum,
//    4-edge unroll (MLP=4 on the gather chain).
__global__ void agg_kernel(int n) {
    int idx = blockIdx.x * blockDim.x + threadIdx.x;
    int node = idx >> 4;          // 16 lanes per node
    int lane = idx & 15;          // lane covers halves [lane*8, lane*8+8)
    if (node >= n) return;

    int beg = g_off[node];
    int end = g_off[node + 1];

    __half2 z = __float2half2_rn(0.f);
    __half2 a0 = z, a1 = z, a2 = z, a3 = z;
    __half2 b0 = z, b1 = z, b2 = z, b3 = z;

    const uint4* fbase = (const uint4*)g_featH;   // one row = 16 uint4
    int e = beg;
    for (; e + 3 < end; e += 4) {
        int s0 = g_csr[e];
        int s1 = g_csr[e + 1];
        int s2 = g_csr[e + 2];
        int s3 = g_csr[e + 3];
        uint4 u0 = fbase[(size_t)s0 * 16 + lane];
        uint4 u1 = fbase[(size_t)s1 * 16 + lane];
        uint4 u2 = fbase[(size_t)s2 * 16 + lane];
        uint4 u3 = fbase[(size_t)s3 * 16 + lane];
        a0 = __hadd2(a0, *(__half2*)&u0.x);
        a1 = __hadd2(a1, *(__half2*)&u0.y);
        a2 = __hadd2(a2, *(__half2*)&u0.z);
        a3 = __hadd2(a3, *(__half2*)&u0.w);
        b0 = __hadd2(b0, *(__half2*)&u1.x);
        b1 = __hadd2(b1, *(__half2*)&u1.y);
        b2 = __hadd2(b2, *(__half2*)&u1.z);
        b3 = __hadd2(b3, *(__half2*)&u1.w);
        a0 = __hadd2(a0, *(__half2*)&u2.x);
        a1 = __hadd2(a1, *(__half2*)&u2.y);
        a2 = __hadd2(a2, *(__half2*)&u2.z);
        a3 = __hadd2(a3, *(__half2*)&u2.w);
        b0 = __hadd2(b0, *(__half2*)&u3.x);
        b1 = __hadd2(b1, *(__half2*)&u3.y);
        b2 = __hadd2(b2, *(__half2*)&u3.z);
        b3 = __hadd2(b3, *(__half2*)&u3.w);
    }
    for (; e < end; ++e) {
        int s0 = g_csr[e];
        uint4 u0 = fbase[(size_t)s0 * 16 + lane];
        a0 = __hadd2(a0, *(__half2*)&u0.x);
        a1 = __hadd2(a1, *(__half2*)&u0.y);
        a2 = __hadd2(a2, *(__half2*)&u0.z);
        a3 = __hadd2(a3, *(__half2*)&u0.w);
    }

    int d = end - beg;
    float scale = 1.0f / (float)(d > 0 ? d : 1);
    float2 f0 = __half22float2(a0), g0 = __half22float2(b0);
    float2 f1 = __half22float2(a1), g1 = __half22float2(b1);
    float2 f2 = __half22float2(a2), g2 = __half22float2(b2);
    float2 f3 = __half22float2(a3), g3 = __half22float2(b3);
    __half2 h0 = __floats2half2_rn((f0.x + g0.x) * scale, (f0.y + g0.y) * scale);
    __half2 h1 = __floats2half2_rn((f1.x + g1.x) * scale, (f1.y + g1.y) * scale);
    __half2 h2 = __floats2half2_rn((f2.x + g2.x) * scale, (f2.y + g2.y) * scale);
    __half2 h3 = __floats2half2_rn((f3.x + g3.x) * scale, (f3.y + g3.y) * scale);
    uint4 o;
    o.x = *(uint32_t*)&h0;
    o.y = *(uint32_t*)&h1;
    o.z = *(uint32_t*)&h2;
    o.w = *(uint32_t*)&h3;
    ((uint4*)g_aggH)[(size_t)node * 16 + lane] = o;
}

// ---------------------------------------------------------------------------
// fp16 tensor-core GEMM (mma.m16n8k16, fp32 accum), software-pipelined:
// out[N,128] = [aggH | featH](N,256) x [W_l ; W_r]^T + b_l
#define GBM 128
#define GKB 32
#define AH_STRIDE 40   // halves
#define BH_STRIDE 40   // halves

__global__ __launch_bounds__(256, 2)
void gemm_tc_kernel(const float* __restrict__ b_l,
                    float* __restrict__ out, int n) {
    __shared__ __half As_h[GBM * AH_STRIDE];   // 10 KB
    __shared__ __half Bs_h[128 * BH_STRIDE];   // 10 KB

    int tid = threadIdx.x;
    int wid = tid >> 5;
    int lane = tid & 31;
    int g = lane >> 2, t = lane & 3;

    int wr = wid & 3;           // warp rows: wr*32 .. +31
    int wc = wid >> 2;          // warp cols: wc*64 .. +63
    int block_row = blockIdx.x * GBM;

    float acc[2][8][4];
#pragma unroll
    for (int nt = 0; nt < 8; ++nt) {
        int c = wc * 64 + nt * 8 + 2 * t;
        float b0 = b_l[c], b1 = b_l[c + 1];
#pragma unroll
        for (int mt = 0; mt < 2; ++mt) {
            acc[mt][nt][0] = b0; acc[mt][nt][1] = b1;
            acc[mt][nt][2] = b0; acc[mt][nt][3] = b1;
        }
    }

    int l_row = tid >> 2;        // 0..63 (+64 on i=1)
    int l_u4 = tid & 3;          // which 8-half slice of the 32-half row

    uint4 rau[2], rbu[2];

    auto load_chunk = [&](int kc) {
        const __half2* Asrc = (kc < 4) ? g_aggH : g_featH;
        int kcol2 = ((kc & 3) * GKB) >> 1;     // half2 offset within row
#pragma unroll
        for (int i = 0; i < 2; ++i) {
            int grow = block_row + l_row + i * 64;
            rau[i] = make_uint4(0u, 0u, 0u, 0u);
            if (grow < n)
                rau[i] = *(const uint4*)&Asrc[(size_t)grow * 64 + kcol2 + l_u4 * 4];
        }
        const __half* Wsrc = g_WH + (kc < 4 ? 0 : 128 * DIM);
        int kbase = (kc & 3) * GKB;
#pragma unroll
        for (int i = 0; i < 2; ++i) {
            int j = l_row + i * 64;
            rbu[i] = *(const uint4*)&Wsrc[(size_t)j * DIM + kbase + l_u4 * 8];
        }
    };

    load_chunk(0);

#pragma unroll 1
    for (int kc = 0; kc < 8; ++kc) {
#pragma unroll
        for (int i = 0; i < 2; ++i) {
            int row = l_row + i * 64;
            *(uint4*)&As_h[row * AH_STRIDE + l_u4 * 8] = rau[i];
            *(uint4*)&Bs_h[row * BH_STRIDE + l_u4 * 8] = rbu[i];
        }
        __syncthreads();

        if (kc < 7) load_chunk(kc + 1);   // overlaps with MMA below

#pragma unroll
        for (int ks = 0; ks < 2; ++ks) {
            int kb = ks * 16;
            uint32_t a[2][4];
#pragma unroll
            for (int mt = 0; mt < 2; ++mt) {
                int rb_ = wr * 32 + mt * 16;
                a[mt][0] = *(const uint32_t*)&As_h[(rb_ + g) * AH_STRIDE + kb + 2 * t];
                a[mt][1] = *(const uint32_t*)&As_h[(rb_ + g + 8) * AH_STRIDE + kb + 2 * t];
                a[mt][2] = *(const uint32_t*)&As_h[(rb_ + g) * AH_STRIDE + kb + 2 * t + 8];
                a[mt][3] = *(const uint32_t*)&As_h[(rb_ + g + 8) * AH_STRIDE + kb + 2 * t + 8];
            }
#pragma unroll
            for (int nt = 0; nt < 8; ++nt) {
                int cb = wc * 64 + nt * 8 + g;
                uint32_t b0 = *(const uint32_t*)&Bs_h[cb * BH_STRIDE + kb + 2 * t];
                uint32_t b1 = *(const uint32_t*)&Bs_h[cb * BH_STRIDE + kb + 2 * t + 8];
#pragma unroll
                for (int mt = 0; mt < 2; ++mt) {
                    asm volatile(
                        "mma.sync.aligned.m16n8k16.row.col.f32.f16.f16.f32 "
                        "{%0,%1,%2,%3}, {%4,%5,%6,%7}, {%8,%9}, {%0,%1,%2,%3};"
                        : "+f"(acc[mt][nt][0]), "+f"(acc[mt][nt][1]),
                          "+f"(acc[mt][nt][2]), "+f"(acc[mt][nt][3])
                        : "r"(a[mt][0]), "r"(a[mt][1]), "r"(a[mt][2]), "r"(a[mt][3]),
                          "r"(b0), "r"(b1));
                }
            }
        }
        __syncthreads();
    }

    // epilogue
#pragma unroll
    for (int mt = 0; mt < 2; ++mt) {
        int r0 = block_row + wr * 32 + mt * 16 + g;
        int r1 = r0 + 8;
#pragma unroll
        for (int nt = 0; nt < 8; ++nt) {
            int c = wc * 64 + nt * 8 + 2 * t;
            if (r0 < n) {
                float2 v = make_float2(acc[mt][nt][0], acc[mt][nt][1]);
                *(float2*)&out[(size_t)r0 * DIM + c] = v;
            }
            if (r1 < n) {
                float2 v = make_float2(acc[mt][nt][2], acc[mt][nt][3]);
                *(float2*)&out[(size_t)r1 * DIM + c] = v;
            }
        }
    }
}

extern "C" void kernel_launch(void* const* d_in, const int* in_sizes, int n_in,
                              void* d_out, int out_size) {
    const float* feature = (const float*)d_in[0];
    const int*   ei      = (const int*)d_in[1];     // int32 (JAX x64 disabled)
    const float* W_l     = (const float*)d_in[2];
    const float* b_l     = (const float*)d_in[3];
    const float* W_r     = (const float*)d_in[4];
    float*       out     = (float*)d_out;

    int N = in_sizes[0] / DIM;
    int E = in_sizes[1] / 2;
    int n2 = N * (DIM / 2);   // half2 count

    void* deg_ptr = nullptr;
    cudaGetSymbolAddress(&deg_ptr, g_deg);
    cudaMemsetAsync(deg_ptr, 0, (size_t)N * sizeof(int), 0);

    hist_conv_kernel<<<(E + 256 * EB - 1) / (256 * EB), 256>>>(
        ei, E, (const float2*)feature, n2, W_l, W_r);

    int nblk = (N + SC_CHUNK - 1) / SC_CHUNK;                    // 49
    off_kernel<<<nblk, SC_BLK>>>(N, E, nblk);
    scatter_kernel<<<(E + 256 * EB - 1) / (256 * EB), 256>>>(ei, E);

    int agg_blocks = (N * 16 + 255) / 256;    // 16 lanes per node
    agg_kernel<<<agg_blocks, 256>>>(N);

    gemm_tc_kernel<<<(N + GBM - 1) / GBM, 256>>>(b_l, out, N);
}

// round 16
// speedup vs baseline: 1.0442x; 1.0442x over previous
#include <cuda_runtime.h>
#include <cuda_bf16.h>
#include <cuda_fp16.h>
#include <stdint.h>

// Problem constants: N=100000 nodes, E=600000 edges, D=128.
#define N_MAX 100000
#define E_MAX 600000
#define DIM   128

// scan geometry
#define SC_BLK   256
#define SC_PER   8
#define SC_CHUNK (SC_BLK * SC_PER)            // 2048
#define SC_NBLK  ((N_MAX + SC_CHUNK - 1) / SC_CHUNK)   // 49 (must stay < 148 for co-residency)

// edge-kernel batching
#define EB 4

// ---- device scratch (no cudaMalloc allowed) ----
__device__ int   g_deg[N_MAX];
__device__ int   g_off[N_MAX + 1];
__device__ int   g_cur[N_MAX];
__device__ int   g_csr[E_MAX];
__device__ int   g_part[64];                                   // partial+1; 0 = not ready
__device__ __align__(16) __half2 g_featH[(size_t)N_MAX * 64];  // fp16 features
__device__ __align__(16) __half2 g_aggH[(size_t)N_MAX * 64];   // fp16 neighbor means
__device__ __align__(16) __half  g_WH[2 * 128 * DIM];          // [0]=W_l, [1]=W_r (row-major j,k)

// ---------------------------------------------------------------------------
// 1) histogram (4 edges/thread) + feature->fp16 (float4 loads) + weights->fp16
__global__ void hist_conv_kernel(const int* __restrict__ ei, int E,
                                 const float4* __restrict__ f4, int n4,
                                 const float* __restrict__ Wl,
                                 const float* __restrict__ Wr) {
    if (blockIdx.x == 0 && threadIdx.x < 64) g_part[threadIdx.x] = 0;

    int base = blockIdx.x * (256 * EB) + threadIdx.x;
    int d[EB];
#pragma unroll
    for (int k = 0; k < EB; ++k) {
        int i = base + k * 256;
        d[k] = (i < E) ? ei[E + i] : -1;
    }
#pragma unroll
    for (int k = 0; k < EB; ++k)
        if (d[k] >= 0 && d[k] < N_MAX) atomicAdd(&g_deg[d[k]], 1);

    int nth = gridDim.x * 256;
    int tid0 = blockIdx.x * 256 + threadIdx.x;
    for (int i = tid0; i < 2 * 128 * DIM; i += nth) {
        float v = (i < 128 * DIM) ? Wl[i] : Wr[i - 128 * DIM];
        g_WH[i] = __float2half_rn(v);
    }
    // features: 16B loads, 8B stores (2 half2 per float4)
    uint2* dstH = (uint2*)g_featH;
    for (int i = tid0; i < n4; i += nth) {
        float4 v = f4[i];
        __half2 h0 = __floats2half2_rn(v.x, v.y);
        __half2 h1 = __floats2half2_rn(v.z, v.w);
        uint2 o;
        o.x = *(uint32_t*)&h0;
        o.y = *(uint32_t*)&h1;
        dstH[i] = o;
    }
}

// 2) single-pass offsets (co-resident spin on chunk partials)
__global__ void off_kernel(int n, int E, int nblk) {
    __shared__ int s_wsum[8];
    __shared__ int s_woff[8];
    __shared__ int s_total;
    __shared__ int sp[64];

    int t = threadIdx.x;
    int lane = t & 31, wid = t >> 5;
    int base = blockIdx.x * SC_CHUNK + t * SC_PER;

    int v[SC_PER];
    int sum = 0;
#pragma unroll
    for (int j = 0; j < SC_PER; ++j) {
        int i = base + j;
        v[j] = (i < n) ? g_deg[i] : 0;
        sum += v[j];
    }

    int inc = sum;
#pragma unroll
    for (int o = 1; o < 32; o <<= 1) {
        int x = __shfl_up_sync(0xffffffffu, inc, o);
        if (lane >= o) inc += x;
    }
    if (lane == 31) s_wsum[wid] = inc;
    __syncthreads();

    if (wid == 0 && lane < 8) {
        int wv = s_wsum[lane];
        int winc = wv;
#pragma unroll
        for (int o = 1; o < 8; o <<= 1) {
            int x = __shfl_up_sync(0xffu, winc, o);
            if (lane >= o) winc += x;
        }
        s_woff[lane] = winc - wv;
        if (lane == 7) s_total = winc;
    }
    __syncthreads();

    if (t == 0) atomicExch(&g_part[blockIdx.x], s_total + 1);

    if (t < 64) {
        int val = 0;
        if (t < nblk) {
            volatile int* gp = g_part;
            while ((val = gp[t]) == 0) { }
            val -= 1;
        }
        sp[t] = val;
    }
    __syncthreads();

#pragma unroll
    for (int o = 1; o < 64; o <<= 1) {
        int tmp = (t < 64 && t >= o) ? sp[t - o] : 0;
        __syncthreads();
        if (t < 64) sp[t] += tmp;
        __syncthreads();
    }
    int chunk_prefix = (blockIdx.x == 0) ? 0 : sp[blockIdx.x - 1];

    int run = chunk_prefix + s_woff[wid] + (inc - sum);
#pragma unroll
    for (int j = 0; j < SC_PER; ++j) {
        int i = base + j;
        if (i < n) {
            g_off[i] = run;
            g_cur[i] = run;
            run += v[j];
        }
    }
    if (blockIdx.x == 0 && t == 0) g_off[n] = E;
}

// 3) scatter src ids into CSR slots — 4 edges/thread
__global__ void scatter_kernel(const int* __restrict__ ei, int E) {
    int base = blockIdx.x * (256 * EB) + threadIdx.x;
    int src[EB], dst[EB];
#pragma unroll
    for (int k = 0; k < EB; ++k) {
        int i = base + k * 256;
        src[k] = (i < E) ? ei[i] : 0;
        dst[k] = (i < E) ? ei[E + i] : -1;
    }
#pragma unroll
    for (int k = 0; k < EB; ++k) {
        if (dst[k] >= 0 && dst[k] < N_MAX) {
            int pos = atomicAdd(&g_cur[dst[k]], 1);
            g_csr[pos] = src[k];
        }
    }
}

// 4) mean aggregation: 16 lanes/node, uint4 loads, HADD2 accum, 4-edge unroll
__global__ void agg_kernel(int n) {
    int idx = blockIdx.x * blockDim.x + threadIdx.x;
    int node = idx >> 4;          // 16 lanes per node
    int lane = idx & 15;          // lane covers halves [lane*8, lane*8+8)
    if (node >= n) return;

    int beg = g_off[node];
    int end = g_off[node + 1];

    __half2 z = __float2half2_rn(0.f);
    __half2 a0 = z, a1 = z, a2 = z, a3 = z;
    __half2 b0 = z, b1 = z, b2 = z, b3 = z;

    const uint4* fbase = (const uint4*)g_featH;   // one row = 16 uint4
    int e = beg;
    for (; e + 3 < end; e += 4) {
        int s0 = g_csr[e];
        int s1 = g_csr[e + 1];
        int s2 = g_csr[e + 2];
        int s3 = g_csr[e + 3];
        uint4 u0 = fbase[(size_t)s0 * 16 + lane];
        uint4 u1 = fbase[(size_t)s1 * 16 + lane];
        uint4 u2 = fbase[(size_t)s2 * 16 + lane];
        uint4 u3 = fbase[(size_t)s3 * 16 + lane];
        a0 = __hadd2(a0, *(__half2*)&u0.x);
        a1 = __hadd2(a1, *(__half2*)&u0.y);
        a2 = __hadd2(a2, *(__half2*)&u0.z);
        a3 = __hadd2(a3, *(__half2*)&u0.w);
        b0 = __hadd2(b0, *(__half2*)&u1.x);
        b1 = __hadd2(b1, *(__half2*)&u1.y);
        b2 = __hadd2(b2, *(__half2*)&u1.z);
        b3 = __hadd2(b3, *(__half2*)&u1.w);
        a0 = __hadd2(a0, *(__half2*)&u2.x);
        a1 = __hadd2(a1, *(__half2*)&u2.y);
        a2 = __hadd2(a2, *(__half2*)&u2.z);
        a3 = __hadd2(a3, *(__half2*)&u2.w);
        b0 = __hadd2(b0, *(__half2*)&u3.x);
        b1 = __hadd2(b1, *(__half2*)&u3.y);
        b2 = __hadd2(b2, *(__half2*)&u3.z);
        b3 = __hadd2(b3, *(__half2*)&u3.w);
    }
    for (; e < end; ++e) {
        int s0 = g_csr[e];
        uint4 u0 = fbase[(size_t)s0 * 16 + lane];
        a0 = __hadd2(a0, *(__half2*)&u0.x);
        a1 = __hadd2(a1, *(__half2*)&u0.y);
        a2 = __hadd2(a2, *(__half2*)&u0.z);
        a3 = __hadd2(a3, *(__half2*)&u0.w);
    }

    int d = end - beg;
    float scale = 1.0f / (float)(d > 0 ? d : 1);
    float2 f0 = __half22float2(a0), g0 = __half22float2(b0);
    float2 f1 = __half22float2(a1), g1 = __half22float2(b1);
    float2 f2 = __half22float2(a2), g2 = __half22float2(b2);
    float2 f3 = __half22float2(a3), g3 = __half22float2(b3);
    __half2 h0 = __floats2half2_rn((f0.x + g0.x) * scale, (f0.y + g0.y) * scale);
    __half2 h1 = __floats2half2_rn((f1.x + g1.x) * scale, (f1.y + g1.y) * scale);
    __half2 h2 = __floats2half2_rn((f2.x + g2.x) * scale, (f2.y + g2.y) * scale);
    __half2 h3 = __floats2half2_rn((f3.x + g3.x) * scale, (f3.y + g3.y) * scale);
    uint4 o;
    o.x = *(uint32_t*)&h0;
    o.y = *(uint32_t*)&h1;
    o.z = *(uint32_t*)&h2;
    o.w = *(uint32_t*)&h3;
    ((uint4*)g_aggH)[(size_t)node * 16 + lane] = o;
}

// ---------------------------------------------------------------------------
// fp16 tensor-core GEMM (mma.m16n8k16, fp32 accum), DOUBLE-BUFFERED smem:
// out[N,128] = [aggH | featH](N,256) x [W_l ; W_r]^T + b_l
// One __syncthreads per K-chunk; LDGs issued 2 chunks ahead.
#define GBM 128
#define GKB 32
#define AH_STRIDE 40   // halves
#define BH_STRIDE 40   // halves

__global__ __launch_bounds__(256, 2)
void gemm_tc_kernel(const float* __restrict__ b_l,
                    float* __restrict__ out, int n) {
    __shared__ __half As_h[2][GBM * AH_STRIDE];   // 2 x 10 KB
    __shared__ __half Bs_h[2][128 * BH_STRIDE];   // 2 x 10 KB

    int tid = threadIdx.x;
    int wid = tid >> 5;
    int lane = tid & 31;
    int g = lane >> 2, t = lane & 3;

    int wr = wid & 3;           // warp rows: wr*32 .. +31
    int wc = wid >> 2;          // warp cols: wc*64 .. +63
    int block_row = blockIdx.x * GBM;

    float acc[2][8][4];
#pragma unroll
    for (int nt = 0; nt < 8; ++nt) {
        int c = wc * 64 + nt * 8 + 2 * t;
        float b0 = b_l[c], b1 = b_l[c + 1];
#pragma unroll
        for (int mt = 0; mt < 2; ++mt) {
            acc[mt][nt][0] = b0; acc[mt][nt][1] = b1;
            acc[mt][nt][2] = b0; acc[mt][nt][3] = b1;
        }
    }

    int l_row = tid >> 2;        // 0..63 (+64 on i=1)
    int l_u4 = tid & 3;          // which 8-half slice of the 32-half row

    uint4 rau[2], rbu[2];

    auto load_chunk = [&](int kc) {
        const __half2* Asrc = (kc < 4) ? g_aggH : g_featH;
        int kcol2 = ((kc & 3) * GKB) >> 1;     // half2 offset within row
#pragma unroll
        for (int i = 0; i < 2; ++i) {
            int grow = block_row + l_row + i * 64;
            rau[i] = make_uint4(0u, 0u, 0u, 0u);
            if (grow < n)
                rau[i] = *(const uint4*)&Asrc[(size_t)grow * 64 + kcol2 + l_u4 * 4];
        }
        const __half* Wsrc = g_WH + (kc < 4 ? 0 : 128 * DIM);
        int kbase = (kc & 3) * GKB;
#pragma unroll
        for (int i = 0; i < 2; ++i) {
            int j = l_row + i * 64;
            rbu[i] = *(const uint4*)&Wsrc[(size_t)j * DIM + kbase + l_u4 * 8];
        }
    };

    auto store_chunk = [&](int buf) {
#pragma unroll
        for (int i = 0; i < 2; ++i) {
            int row = l_row + i * 64;
            *(uint4*)&As_h[buf][row * AH_STRIDE + l_u4 * 8] = rau[i];
            *(uint4*)&Bs_h[buf][row * BH_STRIDE + l_u4 * 8] = rbu[i];
        }
    };

    // prologue: fill buffer 0, prefetch chunk 1 into regs
    load_chunk(0);
    store_chunk(0);
    load_chunk(1);
    __syncthreads();

#pragma unroll 1
    for (int kc = 0; kc < 8; ++kc) {
        int cur = kc & 1;
        if (kc < 7) store_chunk((kc + 1) & 1);   // write idle buffer
        if (kc < 6) load_chunk(kc + 2);          // LDG 2 chunks ahead

#pragma unroll
        for (int ks = 0; ks < 2; ++ks) {
            int kb = ks * 16;
            uint32_t a[2][4];
#pragma unroll
            for (int mt = 0; mt < 2; ++mt) {
                int rb_ = wr * 32 + mt * 16;
                a[mt][0] = *(const uint32_t*)&As_h[cur][(rb_ + g) * AH_STRIDE + kb + 2 * t];
                a[mt][1] = *(const uint32_t*)&As_h[cur][(rb_ + g + 8) * AH_STRIDE + kb + 2 * t];
                a[mt][2] = *(const uint32_t*)&As_h[cur][(rb_ + g) * AH_STRIDE + kb + 2 * t + 8];
                a[mt][3] = *(const uint32_t*)&As_h[cur][(rb_ + g + 8) * AH_STRIDE + kb + 2 * t + 8];
            }
#pragma unroll
            for (int nt = 0; nt < 8; ++nt) {
                int cb = wc * 64 + nt * 8 + g;
                uint32_t b0 = *(const uint32_t*)&Bs_h[cur][cb * BH_STRIDE + kb + 2 * t];
                uint32_t b1 = *(const uint32_t*)&Bs_h[cur][cb * BH_STRIDE + kb + 2 * t + 8];
#pragma unroll
                for (int mt = 0; mt < 2; ++mt) {
                    asm volatile(
                        "mma.sync.aligned.m16n8k16.row.col.f32.f16.f16.f32 "
                        "{%0,%1,%2,%3}, {%4,%5,%6,%7}, {%8,%9}, {%0,%1,%2,%3};"
                        : "+f"(acc[mt][nt][0]), "+f"(acc[mt][nt][1]),
                          "+f"(acc[mt][nt][2]), "+f"(acc[mt][nt][3])
                        : "r"(a[mt][0]), "r"(a[mt][1]), "r"(a[mt][2]), "r"(a[mt][3]),
                          "r"(b0), "r"(b1));
                }
            }
        }
        __syncthreads();   // orders: reads of buf[cur] done; buf[(kc+1)&1] visible
    }

    // epilogue
#pragma unroll
    for (int mt = 0; mt < 2; ++mt) {
        int r0 = block_row + wr * 32 + mt * 16 + g;
        int r1 = r0 + 8;
#pragma unroll
        for (int nt = 0; nt < 8; ++nt) {
            int c = wc * 64 + nt * 8 + 2 * t;
            if (r0 < n) {
                float2 v = make_float2(acc[mt][nt][0], acc[mt][nt][1]);
                *(float2*)&out[(size_t)r0 * DIM + c] = v;
            }
            if (r1 < n) {
                float2 v = make_float2(acc[mt][nt][2], acc[mt][nt][3]);
                *(float2*)&out[(size_t)r1 * DIM + c] = v;
            }
        }
    }
}

extern "C" void kernel_launch(void* const* d_in, const int* in_sizes, int n_in,
                              void* d_out, int out_size) {
    const float* feature = (const float*)d_in[0];
    const int*   ei      = (const int*)d_in[1];     // int32 (JAX x64 disabled)
    const float* W_l     = (const float*)d_in[2];
    const float* b_l     = (const float*)d_in[3];
    const float* W_r     = (const float*)d_in[4];
    float*       out     = (float*)d_out;

    int N = in_sizes[0] / DIM;
    int E = in_sizes[1] / 2;
    int n4 = N * (DIM / 4);   // float4 count

    void* deg_ptr = nullptr;
    cudaGetSymbolAddress(&deg_ptr, g_deg);
    cudaMemsetAsync(deg_ptr, 0, (size_t)N * sizeof(int), 0);

    hist_conv_kernel<<<(E + 256 * EB - 1) / (256 * EB), 256>>>(
        ei, E, (const float4*)feature, n4, W_l, W_r);

    int nblk = (N + SC_CHUNK - 1) / SC_CHUNK;                    // 49
    off_kernel<<<nblk, SC_BLK>>>(N, E, nblk);
    scatter_kernel<<<(E + 256 * EB - 1) / (256 * EB), 256>>>(ei, E);

    int agg_blocks = (N * 16 + 255) / 256;    // 16 lanes per node
    agg_kernel<<<agg_blocks, 256>>>(N);

    gemm_tc_kernel<<<(N + GBM - 1) / GBM, 256>>>(b_l, out, N);
}

// round 17
// speedup vs baseline: 1.0557x; 1.0110x over previous
#include <cuda_runtime.h>
#include <cuda_bf16.h>
#include <cuda_fp16.h>
#include <stdint.h>

// Problem constants: N=100000 nodes, E=600000 edges, D=128.
#define N_MAX 100000
#define E_MAX 600000
#define DIM   128

// scan geometry
#define SC_BLK   256
#define SC_PER   8
#define SC_CHUNK (SC_BLK * SC_PER)            // 2048
#define SC_NBLK  ((N_MAX + SC_CHUNK - 1) / SC_CHUNK)   // 49 (must stay < 148 for co-residency)

// edge-kernel batching
#define EB 4

// ---- device scratch (no cudaMalloc allowed) ----
__device__ int   g_deg[N_MAX];
__device__ int   g_off[N_MAX + 1];
__device__ int   g_rank[E_MAX];                                // per-edge rank within dst
__device__ int   g_csr[E_MAX];
__device__ int   g_part[64];                                   // partial+1; 0 = not ready
__device__ __align__(16) __half2 g_featH[(size_t)N_MAX * 64];  // fp16 features
__device__ __align__(16) __half2 g_aggH[(size_t)N_MAX * 64];   // fp16 neighbor means
__device__ __align__(16) __half  g_WH[2 * 128 * DIM];          // [0]=W_l, [1]=W_r (row-major j,k)

// ---------------------------------------------------------------------------
// 1) histogram (4 edges/thread) storing per-edge rank (atomic return value)
//    + feature->fp16 (float4 loads) + weights->fp16
__global__ void hist_conv_kernel(const int* __restrict__ ei, int E,
                                 const float4* __restrict__ f4, int n4,
                                 const float* __restrict__ Wl,
                                 const float* __restrict__ Wr) {
    if (blockIdx.x == 0 && threadIdx.x < 64) g_part[threadIdx.x] = 0;

    int base = blockIdx.x * (256 * EB) + threadIdx.x;
    int d[EB];
#pragma unroll
    for (int k = 0; k < EB; ++k) {
        int i = base + k * 256;
        d[k] = (i < E) ? ei[E + i] : -1;
    }
#pragma unroll
    for (int k = 0; k < EB; ++k) {
        if (d[k] >= 0 && d[k] < N_MAX) {
            int pos = atomicAdd(&g_deg[d[k]], 1);
            g_rank[base + k * 256] = pos;       // rank of this edge within dst
        }
    }

    int nth = gridDim.x * 256;
    int tid0 = blockIdx.x * 256 + threadIdx.x;
    for (int i = tid0; i < 2 * 128 * DIM; i += nth) {
        float v = (i < 128 * DIM) ? Wl[i] : Wr[i - 128 * DIM];
        g_WH[i] = __float2half_rn(v);
    }
    // features: 16B loads, 8B stores (2 half2 per float4)
    uint2* dstH = (uint2*)g_featH;
    for (int i = tid0; i < n4; i += nth) {
        float4 v = f4[i];
        __half2 h0 = __floats2half2_rn(v.x, v.y);
        __half2 h1 = __floats2half2_rn(v.z, v.w);
        uint2 o;
        o.x = *(uint32_t*)&h0;
        o.y = *(uint32_t*)&h1;
        dstH[i] = o;
    }
}

// 2) single-pass offsets (co-resident spin on chunk partials)
__global__ void off_kernel(int n, int E, int nblk) {
    __shared__ int s_wsum[8];
    __shared__ int s_woff[8];
    __shared__ int s_total;
    __shared__ int sp[64];

    int t = threadIdx.x;
    int lane = t & 31, wid = t >> 5;
    int base = blockIdx.x * SC_CHUNK + t * SC_PER;

    int v[SC_PER];
    int sum = 0;
#pragma unroll
    for (int j = 0; j < SC_PER; ++j) {
        int i = base + j;
        v[j] = (i < n) ? g_deg[i] : 0;
        sum += v[j];
    }

    int inc = sum;
#pragma unroll
    for (int o = 1; o < 32; o <<= 1) {
        int x = __shfl_up_sync(0xffffffffu, inc, o);
        if (lane >= o) inc += x;
    }
    if (lane == 31) s_wsum[wid] = inc;
    __syncthreads();

    if (wid == 0 && lane < 8) {
        int wv = s_wsum[lane];
        int winc = wv;
#pragma unroll
        for (int o = 1; o < 8; o <<= 1) {
            int x = __shfl_up_sync(0xffu, winc, o);
            if (lane >= o) winc += x;
        }
        s_woff[lane] = winc - wv;
        if (lane == 7) s_total = winc;
    }
    __syncthreads();

    if (t == 0) atomicExch(&g_part[blockIdx.x], s_total + 1);

    if (t < 64) {
        int val = 0;
        if (t < nblk) {
            volatile int* gp = g_part;
            while ((val = gp[t]) == 0) { }
            val -= 1;
        }
        sp[t] = val;
    }
    __syncthreads();

#pragma unroll
    for (int o = 1; o < 64; o <<= 1) {
        int tmp = (t < 64 && t >= o) ? sp[t - o] : 0;
        __syncthreads();
        if (t < 64) sp[t] += tmp;
        __syncthreads();
    }
    int chunk_prefix = (blockIdx.x == 0) ? 0 : sp[blockIdx.x - 1];

    int run = chunk_prefix + s_woff[wid] + (inc - sum);
#pragma unroll
    for (int j = 0; j < SC_PER; ++j) {
        int i = base + j;
        if (i < n) {
            g_off[i] = run;
            run += v[j];
        }
    }
    if (blockIdx.x == 0 && t == 0) g_off[n] = E;
}

// 3) scatter src ids into CSR slots — ATOMIC-FREE via precomputed ranks
__global__ void scatter_kernel(const int* __restrict__ ei, int E) {
    int base = blockIdx.x * (256 * EB) + threadIdx.x;
    int src[EB], dst[EB], rnk[EB];
#pragma unroll
    for (int k = 0; k < EB; ++k) {
        int i = base + k * 256;
        src[k] = (i < E) ? ei[i] : 0;
        dst[k] = (i < E) ? ei[E + i] : -1;
        rnk[k] = (i < E) ? g_rank[i] : 0;
    }
    int off[EB];
#pragma unroll
    for (int k = 0; k < EB; ++k)
        off[k] = (dst[k] >= 0 && dst[k] < N_MAX) ? g_off[dst[k]] : 0;
#pragma unroll
    for (int k = 0; k < EB; ++k) {
        if (dst[k] >= 0 && dst[k] < N_MAX)
            g_csr[off[k] + rnk[k]] = src[k];
    }
}

// 4) mean aggregation: 16 lanes/node, uint4 loads, HADD2 accum, 4-edge unroll
__global__ void agg_kernel(int n) {
    int idx = blockIdx.x * blockDim.x + threadIdx.x;
    int node = idx >> 4;          // 16 lanes per node
    int lane = idx & 15;          // lane covers halves [lane*8, lane*8+8)
    if (node >= n) return;

    int beg = g_off[node];
    int end = g_off[node + 1];

    __half2 z = __float2half2_rn(0.f);
    __half2 a0 = z, a1 = z, a2 = z, a3 = z;
    __half2 b0 = z, b1 = z, b2 = z, b3 = z;

    const uint4* fbase = (const uint4*)g_featH;   // one row = 16 uint4
    int e = beg;
    for (; e + 3 < end; e += 4) {
        int s0 = g_csr[e];
        int s1 = g_csr[e + 1];
        int s2 = g_csr[e + 2];
        int s3 = g_csr[e + 3];
        uint4 u0 = fbase[(size_t)s0 * 16 + lane];
        uint4 u1 = fbase[(size_t)s1 * 16 + lane];
        uint4 u2 = fbase[(size_t)s2 * 16 + lane];
        uint4 u3 = fbase[(size_t)s3 * 16 + lane];
        a0 = __hadd2(a0, *(__half2*)&u0.x);
        a1 = __hadd2(a1, *(__half2*)&u0.y);
        a2 = __hadd2(a2, *(__half2*)&u0.z);
        a3 = __hadd2(a3, *(__half2*)&u0.w);
        b0 = __hadd2(b0, *(__half2*)&u1.x);
        b1 = __hadd2(b1, *(__half2*)&u1.y);
        b2 = __hadd2(b2, *(__half2*)&u1.z);
        b3 = __hadd2(b3, *(__half2*)&u1.w);
        a0 = __hadd2(a0, *(__half2*)&u2.x);
        a1 = __hadd2(a1, *(__half2*)&u2.y);
        a2 = __hadd2(a2, *(__half2*)&u2.z);
        a3 = __hadd2(a3, *(__half2*)&u2.w);
        b0 = __hadd2(b0, *(__half2*)&u3.x);
        b1 = __hadd2(b1, *(__half2*)&u3.y);
        b2 = __hadd2(b2, *(__half2*)&u3.z);
        b3 = __hadd2(b3, *(__half2*)&u3.w);
    }
    for (; e < end; ++e) {
        int s0 = g_csr[e];
        uint4 u0 = fbase[(size_t)s0 * 16 + lane];
        a0 = __hadd2(a0, *(__half2*)&u0.x);
        a1 = __hadd2(a1, *(__half2*)&u0.y);
        a2 = __hadd2(a2, *(__half2*)&u0.z);
        a3 = __hadd2(a3, *(__half2*)&u0.w);
    }

    int d = end - beg;
    float scale = 1.0f / (float)(d > 0 ? d : 1);
    float2 f0 = __half22float2(a0), g0 = __half22float2(b0);
    float2 f1 = __half22float2(a1), g1 = __half22float2(b1);
    float2 f2 = __half22float2(a2), g2 = __half22float2(b2);
    float2 f3 = __half22float2(a3), g3 = __half22float2(b3);
    __half2 h0 = __floats2half2_rn((f0.x + g0.x) * scale, (f0.y + g0.y) * scale);
    __half2 h1 = __floats2half2_rn((f1.x + g1.x) * scale, (f1.y + g1.y) * scale);
    __half2 h2 = __floats2half2_rn((f2.x + g2.x) * scale, (f2.y + g2.y) * scale);
    __half2 h3 = __floats2half2_rn((f3.x + g3.x) * scale, (f3.y + g3.y) * scale);
    uint4 o;
    o.x = *(uint32_t*)&h0;
    o.y = *(uint32_t*)&h1;
    o.z = *(uint32_t*)&h2;
    o.w = *(uint32_t*)&h3;
    ((uint4*)g_aggH)[(size_t)node * 16 + lane] = o;
}

// ---------------------------------------------------------------------------
// fp16 tensor-core GEMM (mma.m16n8k16, fp32 accum), double-buffered smem:
// out[N,128] = [aggH | featH](N,256) x [W_l ; W_r]^T + b_l
#define GBM 128
#define GKB 32
#define AH_STRIDE 40   // halves
#define BH_STRIDE 40   // halves

__global__ __launch_bounds__(256, 2)
void gemm_tc_kernel(const float* __restrict__ b_l,
                    float* __restrict__ out, int n) {
    __shared__ __half As_h[2][GBM * AH_STRIDE];   // 2 x 10 KB
    __shared__ __half Bs_h[2][128 * BH_STRIDE];   // 2 x 10 KB

    int tid = threadIdx.x;
    int wid = tid >> 5;
    int lane = tid & 31;
    int g = lane >> 2, t = lane & 3;

    int wr = wid & 3;           // warp rows: wr*32 .. +31
    int wc = wid >> 2;          // warp cols: wc*64 .. +63
    int block_row = blockIdx.x * GBM;

    float acc[2][8][4];
#pragma unroll
    for (int nt = 0; nt < 8; ++nt) {
        int c = wc * 64 + nt * 8 + 2 * t;
        float b0 = b_l[c], b1 = b_l[c + 1];
#pragma unroll
        for (int mt = 0; mt < 2; ++mt) {
            acc[mt][nt][0] = b0; acc[mt][nt][1] = b1;
            acc[mt][nt][2] = b0; acc[mt][nt][3] = b1;
        }
    }

    int l_row = tid >> 2;        // 0..63 (+64 on i=1)
    int l_u4 = tid & 3;          // which 8-half slice of the 32-half row

    uint4 rau[2], rbu[2];

    auto load_chunk = [&](int kc) {
        const __half2* Asrc = (kc < 4) ? g_aggH : g_featH;
        int kcol2 = ((kc & 3) * GKB) >> 1;     // half2 offset within row
#pragma unroll
        for (int i = 0; i < 2; ++i) {
            int grow = block_row + l_row + i * 64;
            rau[i] = make_uint4(0u, 0u, 0u, 0u);
            if (grow < n)
                rau[i] = *(const uint4*)&Asrc[(size_t)grow * 64 + kcol2 + l_u4 * 4];
        }
        const __half* Wsrc = g_WH + (kc < 4 ? 0 : 128 * DIM);
        int kbase = (kc & 3) * GKB;
#pragma unroll
        for (int i = 0; i < 2; ++i) {
            int j = l_row + i * 64;
            rbu[i] = *(const uint4*)&Wsrc[(size_t)j * DIM + kbase + l_u4 * 8];
        }
    };

    auto store_chunk = [&](int buf) {
#pragma unroll
        for (int i = 0; i < 2; ++i) {
            int row = l_row + i * 64;
            *(uint4*)&As_h[buf][row * AH_STRIDE + l_u4 * 8] = rau[i];
            *(uint4*)&Bs_h[buf][row * BH_STRIDE + l_u4 * 8] = rbu[i];
        }
    };

    // prologue: fill buffer 0, prefetch chunk 1 into regs
    load_chunk(0);
    store_chunk(0);
    load_chunk(1);
    __syncthreads();

#pragma unroll 1
    for (int kc = 0; kc < 8; ++kc) {
        int cur = kc & 1;
        if (kc < 7) store_chunk((kc + 1) & 1);   // write idle buffer
        if (kc < 6) load_chunk(kc + 2);          // LDG 2 chunks ahead

#pragma unroll
        for (int ks = 0; ks < 2; ++ks) {
            int kb = ks * 16;
            uint32_t a[2][4];
#pragma unroll
            for (int mt = 0; mt < 2; ++mt) {
                int rb_ = wr * 32 + mt * 16;
                a[mt][0] = *(const uint32_t*)&As_h[cur][(rb_ + g) * AH_STRIDE + kb + 2 * t];
                a[mt][1] = *(const uint32_t*)&As_h[cur][(rb_ + g + 8) * AH_STRIDE + kb + 2 * t];
                a[mt][2] = *(const uint32_t*)&As_h[cur][(rb_ + g) * AH_STRIDE + kb + 2 * t + 8];
                a[mt][3] = *(const uint32_t*)&As_h[cur][(rb_ + g + 8) * AH_STRIDE + kb + 2 * t + 8];
            }
#pragma unroll
            for (int nt = 0; nt < 8; ++nt) {
                int cb = wc * 64 + nt * 8 + g;
                uint32_t b0 = *(const uint32_t*)&Bs_h[cur][cb * BH_STRIDE + kb + 2 * t];
                uint32_t b1 = *(const uint32_t*)&Bs_h[cur][cb * BH_STRIDE + kb + 2 * t + 8];
#pragma unroll
                for (int mt = 0; mt < 2; ++mt) {
                    asm volatile(
                        "mma.sync.aligned.m16n8k16.row.col.f32.f16.f16.f32 "
                        "{%0,%1,%2,%3}, {%4,%5,%6,%7}, {%8,%9}, {%0,%1,%2,%3};"
                        : "+f"(acc[mt][nt][0]), "+f"(acc[mt][nt][1]),
                          "+f"(acc[mt][nt][2]), "+f"(acc[mt][nt][3])
                        : "r"(a[mt][0]), "r"(a[mt][1]), "r"(a[mt][2]), "r"(a[mt][3]),
                          "r"(b0), "r"(b1));
                }
            }
        }
        __syncthreads();
    }

    // epilogue
#pragma unroll
    for (int mt = 0; mt < 2; ++mt) {
        int r0 = block_row + wr * 32 + mt * 16 + g;
        int r1 = r0 + 8;
#pragma unroll
        for (int nt = 0; nt < 8; ++nt) {
            int c = wc * 64 + nt * 8 + 2 * t;
            if (r0 < n) {
                float2 v = make_float2(acc[mt][nt][0], acc[mt][nt][1]);
                *(float2*)&out[(size_t)r0 * DIM + c] = v;
            }
            if (r1 < n) {
                float2 v = make_float2(acc[mt][nt][2], acc[mt][nt][3]);
                *(float2*)&out[(size_t)r1 * DIM + c] = v;
            }
        }
    }
}

extern "C" void kernel_launch(void* const* d_in, const int* in_sizes, int n_in,
                              void* d_out, int out_size) {
    const float* feature = (const float*)d_in[0];
    const int*   ei      = (const int*)d_in[1];     // int32 (JAX x64 disabled)
    const float* W_l     = (const float*)d_in[2];
    const float* b_l     = (const float*)d_in[3];
    const float* W_r     = (const float*)d_in[4];
    float*       out     = (float*)d_out;

    int N = in_sizes[0] / DIM;
    int E = in_sizes[1] / 2;
    int n4 = N * (DIM / 4);   // float4 count

    void* deg_ptr = nullptr;
    cudaGetSymbolAddress(&deg_ptr, g_deg);
    cudaMemsetAsync(deg_ptr, 0, (size_t)N * sizeof(int), 0);

    hist_conv_kernel<<<(E + 256 * EB - 1) / (256 * EB), 256>>>(
        ei, E, (const float4*)feature, n4, W_l, W_r);

    int nblk = (N + SC_CHUNK - 1) / SC_CHUNK;                    // 49
    off_kernel<<<nblk, SC_BLK>>>(N, E, nblk);
    scatter_kernel<<<(E + 256 * EB - 1) / (256 * EB), 256>>>(ei, E);

    int agg_blocks = (N * 16 + 255) / 256;    // 16 lanes per node
    agg_kernel<<<agg_blocks, 256>>>(N);

    gemm_tc_kernel<<<(N + GBM - 1) / GBM, 256>>>(b_l, out, N);
}